// round 1
// baseline (speedup 1.0000x reference)
#include <cuda_runtime.h>
#include <cstdint>

#define NMAX 100000
#define EMAX 1600000
#define DF 64

// ---------------- device scratch (no allocations allowed) ----------------
__device__ float g_K[NMAX * DF];
__device__ float g_Q[NMAX * DF];
__device__ float g_V[NMAX * DF];
__device__ float g_H[NMAX * DF];   // skip-connection output, then += messages
__device__ int   g_src[EMAX];
__device__ int   g_dst[EMAX];
__device__ float g_WT[4 * DF * DF];  // transposed/fused weights: [k][m*64+c]
__device__ float g_sum[DF];
__device__ float g_sumsq[DF];
__device__ int   g_is64;

// ---------------- f32x2 helpers (Blackwell packed fp32) ----------------
__device__ __forceinline__ unsigned long long pk2(float lo, float hi) {
    unsigned long long r;
    asm("mov.b64 %0, {%1,%2};" : "=l"(r) : "f"(lo), "f"(hi));
    return r;
}
__device__ __forceinline__ void fma2(unsigned long long& d, unsigned long long a,
                                     unsigned long long b) {
    asm("fma.rn.f32x2 %0, %1, %2, %0;" : "+l"(d) : "l"(a), "l"(b));
}
__device__ __forceinline__ void upk2(unsigned long long v, float& lo, float& hi) {
    asm("mov.b64 {%0,%1}, %2;" : "=f"(lo), "=f"(hi) : "l"(v));
}

// ---------------- 0: detect int64-vs-int32 edge_index; zero BN sums ----------------
__global__ void init_kernel(const int* __restrict__ ei32, int e) {
    __shared__ int any;
    int t = threadIdx.x;
    if (t == 0) any = 0;
    if (t < DF) { g_sum[t] = 0.0f; g_sumsq[t] = 0.0f; }
    __syncthreads();
    // If edge_index is int64 (values < 2^31, nonneg), every odd int32 word is 0.
    int nz = 0;
    for (int i = t; i < 1024; i += blockDim.x) {
        if (i < e) nz |= ei32[2 * i + 1];
    }
    if (nz) atomicOr(&any, 1);
    __syncthreads();
    if (t == 0) g_is64 = any ? 0 : 1;
}

// ---------------- 1: edge index -> int32 src/dst ----------------
__global__ void convert_kernel(const void* __restrict__ ei, int e) {
    int i = blockIdx.x * blockDim.x + threadIdx.x;
    if (i >= e) return;
    if (g_is64) {
        const long long* p = (const long long*)ei;
        g_src[i] = (int)p[i];
        g_dst[i] = (int)p[e + i];
    } else {
        const int* p = (const int*)ei;
        g_src[i] = p[i];
        g_dst[i] = p[e + i];
    }
}

// ---------------- 2: fuse + transpose weights: g_WT[k][m*64+c] = Wm[c][k] ----------------
__global__ void transw_kernel(const float* __restrict__ Wk, const float* __restrict__ Wq,
                              const float* __restrict__ Wv, const float* __restrict__ Ws) {
    int idx = blockIdx.x * blockDim.x + threadIdx.x;  // 0 .. 16384
    if (idx >= 4 * DF * DF) return;
    int k = idx >> 8;        // 0..63
    int cm = idx & 255;      // m*64 + c
    int m = cm >> 6;
    int c = cm & 63;
    const float* W = (m == 0) ? Wk : (m == 1) ? Wq : (m == 2) ? Wv : Ws;
    g_WT[idx] = W[c * DF + k];
}

// ---------------- 3: fused GEMM: out[n][c] = sum_k x[n][k] * W[c][k] (+bias) --------------
// One launch handles 2 of the 4 matrices (m0 = 0 -> K,Q ; m0 = 2 -> V,H).
// Tile: 32 rows x 128 cols. 256 threads; thread = 2 rows x 8 cols (4 f32x2 accumulator
// pairs per row). Weights staged in smem k-major so LDS.128 reads are conflict-free;
// x tile padded (stride 65) so the two row-broadcasts per warp hit distinct banks.
__global__ void __launch_bounds__(256) gemm_kernel(const float* __restrict__ x,
                                                   const float* __restrict__ b0,
                                                   const float* __restrict__ b1,
                                                   int m0, int n) {
    __shared__ __align__(16) float WTs[64 * 128];
    __shared__ float xs[32 * 65];
    int t = threadIdx.x;
    int row0 = blockIdx.x * 32;

    for (int idx = t; idx < 64 * 128; idx += 256) {
        int k = idx >> 7, cl = idx & 127;
        WTs[idx] = g_WT[k * 256 + m0 * 64 + cl];
    }
    int rows = n - row0; if (rows > 32) rows = 32;
    for (int idx = t; idx < rows * 16; idx += 256) {
        int r = idx >> 4, k4 = idx & 15;
        float4 v = reinterpret_cast<const float4*>(x + (long)(row0 + r) * DF)[k4];
        float* dp = xs + r * 65 + k4 * 4;
        dp[0] = v.x; dp[1] = v.y; dp[2] = v.z; dp[3] = v.w;
    }
    __syncthreads();

    int cg = t & 15;          // column group: 8 cols each, 128 cols total
    int rg = t >> 4;          // row group: 2 rows each, 32 rows total
    int cb = cg * 8;
    int r0 = rg * 2;

    unsigned long long acc[2][4];
#pragma unroll
    for (int r = 0; r < 2; r++)
#pragma unroll
        for (int j = 0; j < 4; j++) acc[r][j] = 0ULL;

#pragma unroll 8
    for (int k = 0; k < 64; k++) {
        const ulonglong2* wp = reinterpret_cast<const ulonglong2*>(WTs + k * 128 + cb);
        ulonglong2 wab = wp[0];
        ulonglong2 wcd = wp[1];
        float xa = xs[r0 * 65 + k];
        float xb = xs[(r0 + 1) * 65 + k];
        unsigned long long xa2 = pk2(xa, xa);
        unsigned long long xb2 = pk2(xb, xb);
        fma2(acc[0][0], xa2, wab.x); fma2(acc[0][1], xa2, wab.y);
        fma2(acc[0][2], xa2, wcd.x); fma2(acc[0][3], xa2, wcd.y);
        fma2(acc[1][0], xb2, wab.x); fma2(acc[1][1], xb2, wab.y);
        fma2(acc[1][2], xb2, wcd.x); fma2(acc[1][3], xb2, wcd.y);
    }

    int mloc = cg >> 3;  // 0 or 1 within this launch
    float* outp = (m0 == 0) ? (mloc ? g_Q : g_K) : (mloc ? g_H : g_V);
    const float* bp = mloc ? b1 : b0;
    int cin = cb & 63;
    float bias[8];
#pragma unroll
    for (int j = 0; j < 8; j++) bias[j] = bp[cin + j];

#pragma unroll
    for (int r = 0; r < 2; r++) {
        int row = row0 + r0 + r;
        if (row < n) {
            float v[8];
#pragma unroll
            for (int j = 0; j < 4; j++) upk2(acc[r][j], v[2 * j], v[2 * j + 1]);
#pragma unroll
            for (int j = 0; j < 8; j++) v[j] += bias[j];
            float4* op = reinterpret_cast<float4*>(outp + (long)row * DF + cin);
            op[0] = make_float4(v[0], v[1], v[2], v[3]);
            op[1] = make_float4(v[4], v[5], v[6], v[7]);
        }
    }
}

// ---------------- 4: edge gather + gate + vector-atomic scatter ----------------
// 16 threads per edge, each thread handles 4 features (float4). K/Q/V live in L2.
__global__ void __launch_bounds__(256) edge_kernel(int e) {
    int idx = blockIdx.x * blockDim.x + threadIdx.x;
    if (idx >= e * 16) return;
    int ed = idx >> 4;
    int c4 = idx & 15;
    int s = g_src[ed];
    int dv = g_dst[ed];
    const float4* Kp = reinterpret_cast<const float4*>(g_K);
    const float4* Qp = reinterpret_cast<const float4*>(g_Q);
    const float4* Vp = reinterpret_cast<const float4*>(g_V);
    float4 kk = __ldg(&Kp[dv * 16 + c4]);
    float4 qq = __ldg(&Qp[s * 16 + c4]);
    float4 vv = __ldg(&Vp[s * 16 + c4]);
    float4 m;
    m.x = vv.x / (1.0f + __expf(-(kk.x + qq.x)));
    m.y = vv.y / (1.0f + __expf(-(kk.y + qq.y)));
    m.z = vv.z / (1.0f + __expf(-(kk.z + qq.z)));
    m.w = vv.w / (1.0f + __expf(-(kk.w + qq.w)));
    atomicAdd(reinterpret_cast<float4*>(g_H) + dv * 16 + c4, m);
}

// ---------------- 5: BatchNorm statistics (per-column sum / sumsq) ----------------
__global__ void __launch_bounds__(256) stats_kernel(int n) {
    __shared__ float ss[256], ss2[256];
    int t = threadIdx.x;
    int col = t & 63;
    int q = t >> 6;  // 0..3
    float s = 0.0f, s2 = 0.0f;
    for (int r = blockIdx.x * 4 + q; r < n; r += gridDim.x * 4) {
        float v = g_H[(long)r * DF + col];
        s += v;
        s2 += v * v;
    }
    ss[t] = s; ss2[t] = s2;
    __syncthreads();
    if (t < 64) {
        float ts = ss[t] + ss[t + 64] + ss[t + 128] + ss[t + 192];
        float ts2 = ss2[t] + ss2[t + 64] + ss2[t + 128] + ss2[t + 192];
        atomicAdd(&g_sum[t], ts);
        atomicAdd(&g_sumsq[t], ts2);
    }
}

// ---------------- 6: BN affine + ReLU + residual ----------------
__global__ void __launch_bounds__(256) out_kernel(const float* __restrict__ x,
                                                  const float* __restrict__ gamma,
                                                  const float* __restrict__ beta,
                                                  float* __restrict__ out, int n) {
    __shared__ float sc[64], sh[64];
    int t = threadIdx.x;
    if (t < 64) {
        float invn = 1.0f / (float)n;
        float mean = g_sum[t] * invn;
        float var = g_sumsq[t] * invn - mean * mean;
        float s = gamma[t] * rsqrtf(var + 1e-5f);
        sc[t] = s;
        sh[t] = beta[t] - mean * s;
    }
    __syncthreads();
    const float4* H4 = reinterpret_cast<const float4*>(g_H);
    const float4* X4 = reinterpret_cast<const float4*>(x);
    float4* O4 = reinterpret_cast<float4*>(out);
    int total = n * 16;
    for (int i = blockIdx.x * blockDim.x + t; i < total; i += gridDim.x * blockDim.x) {
        int col = (i & 15) * 4;
        float4 h = H4[i];
        float4 xv = X4[i];
        float4 o;
        o.x = fmaxf(h.x * sc[col + 0] + sh[col + 0], 0.0f) + xv.x;
        o.y = fmaxf(h.y * sc[col + 1] + sh[col + 1], 0.0f) + xv.y;
        o.z = fmaxf(h.z * sc[col + 2] + sh[col + 2], 0.0f) + xv.z;
        o.w = fmaxf(h.w * sc[col + 3] + sh[col + 3], 0.0f) + xv.w;
        O4[i] = o;
    }
}

// ---------------- launch ----------------
extern "C" void kernel_launch(void* const* d_in, const int* in_sizes, int n_in,
                              void* d_out, int out_size) {
    const float* x     = (const float*)d_in[0];
    const void*  ei    = d_in[1];
    const float* Wk    = (const float*)d_in[2];
    const float* bk    = (const float*)d_in[3];
    const float* Wq    = (const float*)d_in[4];
    const float* bq    = (const float*)d_in[5];
    const float* Wv    = (const float*)d_in[6];
    const float* bv    = (const float*)d_in[7];
    const float* Ws    = (const float*)d_in[8];
    const float* bs    = (const float*)d_in[9];
    const float* gamma = (const float*)d_in[10];
    const float* beta  = (const float*)d_in[11];

    int n = in_sizes[0] / DF;
    int e = in_sizes[1] / 2;

    init_kernel<<<1, 256>>>((const int*)ei, e);
    convert_kernel<<<(e + 255) / 256, 256>>>(ei, e);
    transw_kernel<<<(4 * DF * DF + 255) / 256, 256>>>(Wk, Wq, Wv, Ws);

    int gblocks = (n + 31) / 32;
    gemm_kernel<<<gblocks, 256>>>(x, bk, bq, 0, n);  // -> g_K, g_Q
    gemm_kernel<<<gblocks, 256>>>(x, bv, bs, 2, n);  // -> g_V, g_H (skip + bias)

    edge_kernel<<<(e * 16 + 255) / 256, 256>>>(e);
    stats_kernel<<<1024, 256>>>(n);
    out_kernel<<<2048, 256>>>(x, gamma, beta, (float*)d_out, n);
}

// round 2
// speedup vs baseline: 1.5351x; 1.5351x over previous
#include <cuda_runtime.h>
#include <cstdint>

#define NMAX 100000
#define EMAX 1600000
#define DF 64

// ---------------- device scratch (no allocations allowed) ----------------
__device__ float g_K[NMAX * DF];
__device__ float g_Q[NMAX * DF];
__device__ float g_V[NMAX * DF];
__device__ float g_H[NMAX * DF];   // skip-connection output, then += messages
__device__ int   g_src[EMAX];
__device__ int   g_dst[EMAX];
__device__ float g_WT[4 * DF * DF];  // transposed/fused weights: [k][m*64+c]
__device__ float g_sum[DF];
__device__ float g_sumsq[DF];
__device__ int   g_is64;

// ---------------- f32x2 helpers (Blackwell packed fp32) ----------------
__device__ __forceinline__ unsigned long long pk2(float lo, float hi) {
    unsigned long long r;
    asm("mov.b64 %0, {%1,%2};" : "=l"(r) : "f"(lo), "f"(hi));
    return r;
}
__device__ __forceinline__ void fma2(unsigned long long& d, unsigned long long a,
                                     unsigned long long b) {
    asm("fma.rn.f32x2 %0, %1, %2, %0;" : "+l"(d) : "l"(a), "l"(b));
}
__device__ __forceinline__ void upk2(unsigned long long v, float& lo, float& hi) {
    asm("mov.b64 {%0,%1}, %2;" : "=f"(lo), "=f"(hi) : "l"(v));
}

// ---------------- 0: detect int64-vs-int32 edge_index; zero BN sums ----------------
__global__ void init_kernel(const int* __restrict__ ei32, int e) {
    __shared__ int any;
    int t = threadIdx.x;
    if (t == 0) any = 0;
    if (t < DF) { g_sum[t] = 0.0f; g_sumsq[t] = 0.0f; }
    __syncthreads();
    int nz = 0;
    for (int i = t; i < 1024; i += blockDim.x) {
        if (i < e) nz |= ei32[2 * i + 1];
    }
    if (nz) atomicOr(&any, 1);
    __syncthreads();
    if (t == 0) g_is64 = any ? 0 : 1;
}

// ---------------- 1: edge index -> int32 src/dst ----------------
__global__ void convert_kernel(const void* __restrict__ ei, int e) {
    int i = blockIdx.x * blockDim.x + threadIdx.x;
    if (i >= e) return;
    if (g_is64) {
        const long long* p = (const long long*)ei;
        g_src[i] = (int)p[i];
        g_dst[i] = (int)p[e + i];
    } else {
        const int* p = (const int*)ei;
        g_src[i] = p[i];
        g_dst[i] = p[e + i];
    }
}

// ---------------- 2: fuse + transpose weights: g_WT[k][m*64+c] = Wm[c][k] ----------------
__global__ void transw_kernel(const float* __restrict__ Wk, const float* __restrict__ Wq,
                              const float* __restrict__ Wv, const float* __restrict__ Ws) {
    int idx = blockIdx.x * blockDim.x + threadIdx.x;  // 0 .. 16384
    if (idx >= 4 * DF * DF) return;
    int k = idx >> 8;        // 0..63
    int cm = idx & 255;      // m*64 + c
    int m = cm >> 6;
    int c = cm & 63;
    const float* W = (m == 0) ? Wk : (m == 1) ? Wq : (m == 2) ? Wv : Ws;
    g_WT[idx] = W[c * DF + k];
}

// ---------------- 3: fused GEMM: out[n][c] = sum_k x[n][k] * W[c][k] (+bias) --------------
// Block tile: 128 rows x 128 cols (2 matrices per launch). 256 threads.
// Thread tile: 4 rows x 16 cols = 64 outputs (32 f32x2 accumulators).
//   Warp = 8 colgroups x 4 rowgroups.
//   Thread's 16 cols = 4 chunks of 4 at {cg*4 + j*32}: weight LDS.128 per instr
//     covers a contiguous 128B across the warp -> 1 wavefront, conflict-free.
//   Thread's 4 rows = {wbase + rgl + 4i}: x LDS.128 (float4 over k) per instr hits
//     4 consecutive rows at smem stride 72 floats -> bank phases 0/8/16/24,
//     conflict-free, broadcast across colgroups.
// Per 4k per warp: 20 smem wavefronts vs 128 f32x2 (256 SMSP-cyc) -> fma-bound.
#define XS_STRIDE 72
#define GEMM_SMEM (64 * 128 * 4 + 128 * XS_STRIDE * 4)

__global__ void __launch_bounds__(256) gemm_kernel(const float* __restrict__ x,
                                                   const float* __restrict__ b0,
                                                   const float* __restrict__ b1,
                                                   int m0, int n) {
    extern __shared__ float sm[];
    float* WTs = sm;                 // [64][128]
    float* xs  = sm + 64 * 128;      // [128][XS_STRIDE]
    int t = threadIdx.x;
    int row0 = blockIdx.x * 128;

    // Stage weights (k-major, 128 cols = 2 matrices starting at m0*64)
    for (int idx = t; idx < 64 * 32; idx += 256) {   // float4 granularity
        int k = idx >> 5;
        int c4 = idx & 31;
        float4 v = *reinterpret_cast<const float4*>(&g_WT[k * 256 + m0 * 64 + c4 * 4]);
        *reinterpret_cast<float4*>(&WTs[k * 128 + c4 * 4]) = v;
    }
    // Stage x rows
    int rows = n - row0; if (rows > 128) rows = 128;
    for (int idx = t; idx < rows * 16; idx += 256) {
        int r = idx >> 4, k4 = idx & 15;
        float4 v = reinterpret_cast<const float4*>(x + (size_t)(row0 + r) * DF)[k4];
        *reinterpret_cast<float4*>(&xs[r * XS_STRIDE + k4 * 4]) = v;
    }
    __syncthreads();

    int lane = t & 31, warp = t >> 5;
    int cg = lane & 7;        // colgroup 0..7
    int rgl = lane >> 3;      // rowgroup-in-warp 0..3
    int rbase = warp * 16 + rgl;   // thread rows: rbase + 4*i

    unsigned long long acc[4][4][2];
#pragma unroll
    for (int i = 0; i < 4; i++)
#pragma unroll
        for (int j = 0; j < 4; j++) { acc[i][j][0] = 0ULL; acc[i][j][1] = 0ULL; }

    for (int kc = 0; kc < 64; kc += 4) {
        float4 xv[4];
#pragma unroll
        for (int i = 0; i < 4; i++)
            xv[i] = *reinterpret_cast<const float4*>(&xs[(rbase + 4 * i) * XS_STRIDE + kc]);
#pragma unroll
        for (int kk = 0; kk < 4; kk++) {
            unsigned long long wj[4][2];
#pragma unroll
            for (int j = 0; j < 4; j++) {
                ulonglong2 wv = *reinterpret_cast<const ulonglong2*>(
                    &WTs[(kc + kk) * 128 + j * 32 + cg * 4]);
                wj[j][0] = wv.x; wj[j][1] = wv.y;
            }
#pragma unroll
            for (int i = 0; i < 4; i++) {
                float xk = (kk == 0) ? xv[i].x : (kk == 1) ? xv[i].y
                         : (kk == 2) ? xv[i].z : xv[i].w;
                unsigned long long x2 = pk2(xk, xk);
#pragma unroll
                for (int j = 0; j < 4; j++) {
                    fma2(acc[i][j][0], x2, wj[j][0]);
                    fma2(acc[i][j][1], x2, wj[j][1]);
                }
            }
        }
    }

    // Epilogue: bias + store. j<2 -> first matrix, j>=2 -> second.
    float* out0 = (m0 == 0) ? g_K : g_V;
    float* out1 = (m0 == 0) ? g_Q : g_H;
    float bias[4][4];
#pragma unroll
    for (int j = 0; j < 4; j++) {
        const float* bp = (j < 2) ? b0 : b1;
        int cin = cg * 4 + (j & 1) * 32;
#pragma unroll
        for (int w = 0; w < 4; w++) bias[j][w] = bp[cin + w];
    }
#pragma unroll
    for (int i = 0; i < 4; i++) {
        int row = row0 + rbase + 4 * i;
        if (row < n) {
#pragma unroll
            for (int j = 0; j < 4; j++) {
                float v0, v1, v2, v3;
                upk2(acc[i][j][0], v0, v1);
                upk2(acc[i][j][1], v2, v3);
                float* outp = (j < 2) ? out0 : out1;
                int cin = cg * 4 + (j & 1) * 32;
                *reinterpret_cast<float4*>(outp + (size_t)row * DF + cin) =
                    make_float4(v0 + bias[j][0], v1 + bias[j][1],
                                v2 + bias[j][2], v3 + bias[j][3]);
            }
        }
    }
}

// ---------------- 4: edge gather + gate + vector-atomic scatter ----------------
__global__ void __launch_bounds__(256) edge_kernel(int e) {
    int idx = blockIdx.x * blockDim.x + threadIdx.x;
    if (idx >= e * 16) return;
    int ed = idx >> 4;
    int c4 = idx & 15;
    int s = g_src[ed];
    int dv = g_dst[ed];
    const float4* Kp = reinterpret_cast<const float4*>(g_K);
    const float4* Qp = reinterpret_cast<const float4*>(g_Q);
    const float4* Vp = reinterpret_cast<const float4*>(g_V);
    float4 kk = __ldg(&Kp[dv * 16 + c4]);
    float4 qq = __ldg(&Qp[s * 16 + c4]);
    float4 vv = __ldg(&Vp[s * 16 + c4]);
    float4 m;
    m.x = vv.x / (1.0f + __expf(-(kk.x + qq.x)));
    m.y = vv.y / (1.0f + __expf(-(kk.y + qq.y)));
    m.z = vv.z / (1.0f + __expf(-(kk.z + qq.z)));
    m.w = vv.w / (1.0f + __expf(-(kk.w + qq.w)));
    atomicAdd(reinterpret_cast<float4*>(g_H) + dv * 16 + c4, m);
}

// ---------------- 5: BatchNorm statistics (per-column sum / sumsq) ----------------
__global__ void __launch_bounds__(256) stats_kernel(int n) {
    __shared__ float ss[256], ss2[256];
    int t = threadIdx.x;
    int col = t & 63;
    int q = t >> 6;  // 0..3
    float s = 0.0f, s2 = 0.0f;
    for (int r = blockIdx.x * 4 + q; r < n; r += gridDim.x * 4) {
        float v = g_H[(long)r * DF + col];
        s += v;
        s2 += v * v;
    }
    ss[t] = s; ss2[t] = s2;
    __syncthreads();
    if (t < 64) {
        float ts = ss[t] + ss[t + 64] + ss[t + 128] + ss[t + 192];
        float ts2 = ss2[t] + ss2[t + 64] + ss2[t + 128] + ss2[t + 192];
        atomicAdd(&g_sum[t], ts);
        atomicAdd(&g_sumsq[t], ts2);
    }
}

// ---------------- 6: BN affine + ReLU + residual ----------------
__global__ void __launch_bounds__(256) out_kernel(const float* __restrict__ x,
                                                  const float* __restrict__ gamma,
                                                  const float* __restrict__ beta,
                                                  float* __restrict__ out, int n) {
    __shared__ float sc[64], sh[64];
    int t = threadIdx.x;
    if (t < 64) {
        float invn = 1.0f / (float)n;
        float mean = g_sum[t] * invn;
        float var = g_sumsq[t] * invn - mean * mean;
        float s = gamma[t] * rsqrtf(var + 1e-5f);
        sc[t] = s;
        sh[t] = beta[t] - mean * s;
    }
    __syncthreads();
    const float4* H4 = reinterpret_cast<const float4*>(g_H);
    const float4* X4 = reinterpret_cast<const float4*>(x);
    float4* O4 = reinterpret_cast<float4*>(out);
    int total = n * 16;
    for (int i = blockIdx.x * blockDim.x + t; i < total; i += gridDim.x * blockDim.x) {
        int col = (i & 15) * 4;
        float4 h = H4[i];
        float4 xv = X4[i];
        float4 o;
        o.x = fmaxf(h.x * sc[col + 0] + sh[col + 0], 0.0f) + xv.x;
        o.y = fmaxf(h.y * sc[col + 1] + sh[col + 1], 0.0f) + xv.y;
        o.z = fmaxf(h.z * sc[col + 2] + sh[col + 2], 0.0f) + xv.z;
        o.w = fmaxf(h.w * sc[col + 3] + sh[col + 3], 0.0f) + xv.w;
        O4[i] = o;
    }
}

// ---------------- launch ----------------
extern "C" void kernel_launch(void* const* d_in, const int* in_sizes, int n_in,
                              void* d_out, int out_size) {
    const float* x     = (const float*)d_in[0];
    const void*  ei    = d_in[1];
    const float* Wk    = (const float*)d_in[2];
    const float* bk    = (const float*)d_in[3];
    const float* Wq    = (const float*)d_in[4];
    const float* bq    = (const float*)d_in[5];
    const float* Wv    = (const float*)d_in[6];
    const float* bv    = (const float*)d_in[7];
    const float* Ws    = (const float*)d_in[8];
    const float* bs    = (const float*)d_in[9];
    const float* gamma = (const float*)d_in[10];
    const float* beta  = (const float*)d_in[11];

    int n = in_sizes[0] / DF;
    int e = in_sizes[1] / 2;

    static bool attr_done = false;
    if (!attr_done) {
        cudaFuncSetAttribute(gemm_kernel, cudaFuncAttributeMaxDynamicSharedMemorySize,
                             GEMM_SMEM);
        attr_done = true;
    }

    init_kernel<<<1, 256>>>((const int*)ei, e);
    convert_kernel<<<(e + 255) / 256, 256>>>(ei, e);
    transw_kernel<<<(4 * DF * DF + 255) / 256, 256>>>(Wk, Wq, Wv, Ws);

    int gblocks = (n + 127) / 128;
    gemm_kernel<<<gblocks, 256, GEMM_SMEM>>>(x, bk, bq, 0, n);  // -> g_K, g_Q
    gemm_kernel<<<gblocks, 256, GEMM_SMEM>>>(x, bv, bs, 2, n);  // -> g_V, g_H

    edge_kernel<<<(e * 16 + 255) / 256, 256>>>(e);
    stats_kernel<<<1024, 256>>>(n);
    out_kernel<<<2048, 256>>>(x, gamma, beta, (float*)d_out, n);
}

// round 5
// speedup vs baseline: 1.7790x; 1.1589x over previous
#include <cuda_runtime.h>
#include <cuda_fp16.h>
#include <cstdint>

#define NMAX 100000
#define EMAX 1600000
#define DF 64

// ---------------- device scratch (no allocations allowed) ----------------
__device__ __half g_Kh[NMAX * DF];
__device__ __half g_Qh[NMAX * DF];
__device__ __half g_Vh[NMAX * DF];
__device__ float  g_H[NMAX * DF];   // fp32: skip-connection, then += messages
__device__ int   g_src[EMAX];
__device__ int   g_dst[EMAX];
__device__ float g_WT[4 * DF * DF];  // transposed/fused weights: [k][m*64+c]
__device__ float g_sum[DF];
__device__ float g_sumsq[DF];
__device__ int   g_is64;

// ---------------- f32x2 helpers (Blackwell packed fp32) ----------------
__device__ __forceinline__ unsigned long long pk2(float lo, float hi) {
    unsigned long long r;
    asm("mov.b64 %0, {%1,%2};" : "=l"(r) : "f"(lo), "f"(hi));
    return r;
}
__device__ __forceinline__ void fma2(unsigned long long& d, unsigned long long a,
                                     unsigned long long b) {
    asm("fma.rn.f32x2 %0, %1, %2, %0;" : "+l"(d) : "l"(a), "l"(b));
}
__device__ __forceinline__ void upk2(unsigned long long v, float& lo, float& hi) {
    asm("mov.b64 {%0,%1}, %2;" : "=f"(lo), "=f"(hi) : "l"(v));
}

// ---------------- 0: detect int64-vs-int32 edge_index; zero BN sums ----------------
__global__ void init_kernel(const int* __restrict__ ei32, int e) {
    __shared__ int any;
    int t = threadIdx.x;
    if (t == 0) any = 0;
    if (t < DF) { g_sum[t] = 0.0f; g_sumsq[t] = 0.0f; }
    __syncthreads();
    int nz = 0;
    for (int i = t; i < 1024; i += blockDim.x) {
        if (i < e) nz |= ei32[2 * i + 1];
    }
    if (nz) atomicOr(&any, 1);
    __syncthreads();
    if (t == 0) g_is64 = any ? 0 : 1;
}

// ---------------- 1: edge index -> int32 src/dst ----------------
__global__ void convert_kernel(const void* __restrict__ ei, int e) {
    int i = blockIdx.x * blockDim.x + threadIdx.x;
    if (i >= e) return;
    if (g_is64) {
        const long long* p = (const long long*)ei;
        g_src[i] = (int)p[i];
        g_dst[i] = (int)p[e + i];
    } else {
        const int* p = (const int*)ei;
        g_src[i] = p[i];
        g_dst[i] = p[e + i];
    }
}

// ---------------- 2: fuse + transpose weights: g_WT[k][m*64+c] = Wm[c][k] ----------------
__global__ void transw_kernel(const float* __restrict__ Wk, const float* __restrict__ Wq,
                              const float* __restrict__ Wv, const float* __restrict__ Ws) {
    int idx = blockIdx.x * blockDim.x + threadIdx.x;  // 0 .. 16384
    if (idx >= 4 * DF * DF) return;
    int k = idx >> 8;        // 0..63
    int cm = idx & 255;      // m*64 + c
    int m = cm >> 6;
    int c = cm & 63;
    const float* W = (m == 0) ? Wk : (m == 1) ? Wq : (m == 2) ? Wv : Ws;
    g_WT[idx] = W[c * DF + k];
}

// ---------------- 3: fused GEMM: out[n][c] = sum_k x[n][k] * W[c][k] (+bias) --------------
// Block: 256 rows x 64 cols (one matrix, blockIdx.y selects which of the pair).
// 256 threads = 8 warps, each warp 32 rows x 64 cols. Thread: 8 rows x 8 cols
// (rows rbase+4i; cols {cg*4, 32+cg*4} chunks). Per warp per 4k: 8 x-LDS.128 +
// 8 w-LDS.128 = 16 (vs 128 fma2) -> smem crossbar no longer the limiter.
//   w-LDS: 8 cg lanes cover contiguous 128B, rg broadcast -> conflict-free.
//   x-LDS: 4 distinct rows at stride 72 floats -> bank phases 0/8/16/24 -> clean.
#define XS_STRIDE 72
#define RPB 256
#define GEMM_SMEM (64 * 64 * 4 + RPB * XS_STRIDE * 4)

__global__ void __launch_bounds__(256) gemm_kernel(const float* __restrict__ x,
                                                   const float* __restrict__ b0,
                                                   const float* __restrict__ b1,
                                                   int m0, int n) {
    extern __shared__ float sm[];
    float* Ws = sm;                 // [64][64]
    float* xs = sm + 64 * 64;       // [RPB][XS_STRIDE]
    int t = threadIdx.x;
    int matrix = blockIdx.y;        // 0 or 1
    int m = m0 + matrix;            // 0..3 -> Kh, Qh, Vh, H
    int row0 = blockIdx.x * RPB;

    for (int idx = t; idx < 64 * 16; idx += 256) {
        int k = idx >> 4, c4 = idx & 15;
        float4 v = *reinterpret_cast<const float4*>(&g_WT[k * 256 + m * 64 + c4 * 4]);
        *reinterpret_cast<float4*>(&Ws[k * 64 + c4 * 4]) = v;
    }
    int rows = n - row0; if (rows > RPB) rows = RPB;
    for (int idx = t; idx < rows * 16; idx += 256) {
        int r = idx >> 4, k4 = idx & 15;
        float4 v = reinterpret_cast<const float4*>(x + (size_t)(row0 + r) * DF)[k4];
        *reinterpret_cast<float4*>(&xs[r * XS_STRIDE + k4 * 4]) = v;
    }
    __syncthreads();

    int lane = t & 31, warp = t >> 5;
    int cg = lane & 7;        // colgroup 0..7
    int rg = lane >> 3;       // rowgroup 0..3
    int rbase = warp * 32 + rg;    // thread rows: rbase + 4*i, i<8

    unsigned long long acc[8][4];
#pragma unroll
    for (int i = 0; i < 8; i++)
#pragma unroll
        for (int j = 0; j < 4; j++) acc[i][j] = 0ULL;

    for (int kc = 0; kc < 64; kc += 4) {
        float4 xv[8];
#pragma unroll
        for (int i = 0; i < 8; i++)
            xv[i] = *reinterpret_cast<const float4*>(&xs[(rbase + 4 * i) * XS_STRIDE + kc]);
#pragma unroll
        for (int kk = 0; kk < 4; kk++) {
            ulonglong2 w0 = *reinterpret_cast<const ulonglong2*>(&Ws[(kc + kk) * 64 + cg * 4]);
            ulonglong2 w1 = *reinterpret_cast<const ulonglong2*>(&Ws[(kc + kk) * 64 + 32 + cg * 4]);
#pragma unroll
            for (int i = 0; i < 8; i++) {
                float xk = (kk == 0) ? xv[i].x : (kk == 1) ? xv[i].y
                         : (kk == 2) ? xv[i].z : xv[i].w;
                unsigned long long x2 = pk2(xk, xk);
                fma2(acc[i][0], x2, w0.x); fma2(acc[i][1], x2, w0.y);
                fma2(acc[i][2], x2, w1.x); fma2(acc[i][3], x2, w1.y);
            }
        }
    }

    // Epilogue: bias, then fp16 store (K/Q/V) or fp32 store (H).
    const float* bp = matrix ? b1 : b0;
    int c0 = cg * 4;       // chunk 0 cols c0..c0+3
    int c1 = 32 + cg * 4;  // chunk 1
    float bias[8];
#pragma unroll
    for (int w = 0; w < 4; w++) { bias[w] = bp[c0 + w]; bias[4 + w] = bp[c1 + w]; }

    __half* outh = (m == 0) ? g_Kh : (m == 1) ? g_Qh : g_Vh;
    bool is_half = (m != 3);

#pragma unroll
    for (int i = 0; i < 8; i++) {
        int row = row0 + rbase + 4 * i;
        if (row < n) {
            float v[8];
            upk2(acc[i][0], v[0], v[1]); upk2(acc[i][1], v[2], v[3]);
            upk2(acc[i][2], v[4], v[5]); upk2(acc[i][3], v[6], v[7]);
#pragma unroll
            for (int w = 0; w < 8; w++) v[w] += bias[w];
            if (is_half) {
                __half2 h0 = __floats2half2_rn(v[0], v[1]);
                __half2 h1 = __floats2half2_rn(v[2], v[3]);
                __half2 h2 = __floats2half2_rn(v[4], v[5]);
                __half2 h3 = __floats2half2_rn(v[6], v[7]);
                uint2 u0, u1;
                u0.x = reinterpret_cast<unsigned&>(h0);
                u0.y = reinterpret_cast<unsigned&>(h1);
                u1.x = reinterpret_cast<unsigned&>(h2);
                u1.y = reinterpret_cast<unsigned&>(h3);
                *reinterpret_cast<uint2*>(outh + (size_t)row * DF + c0) = u0;
                *reinterpret_cast<uint2*>(outh + (size_t)row * DF + c1) = u1;
            } else {
                *reinterpret_cast<float4*>(g_H + (size_t)row * DF + c0) =
                    make_float4(v[0], v[1], v[2], v[3]);
                *reinterpret_cast<float4*>(g_H + (size_t)row * DF + c1) =
                    make_float4(v[4], v[5], v[6], v[7]);
            }
        }
    }
}

// ---------------- 4: edge gather (fp16) + gate + fp32 vector-atomic scatter --------------
// 8 threads per edge; each handles 8 features (16B fp16 loads -> one 128B L2 line
// per array per edge). Atomics stay fp32 (2x float4 per thread).
__global__ void __launch_bounds__(256) edge_kernel(int e) {
    int idx = blockIdx.x * blockDim.x + threadIdx.x;
    if (idx >= e * 8) return;
    int ed = idx >> 3;
    int c = idx & 7;
    int s = g_src[ed];
    int dv = g_dst[ed];
    const uint4* Kp = reinterpret_cast<const uint4*>(g_Kh);
    const uint4* Qp = reinterpret_cast<const uint4*>(g_Qh);
    const uint4* Vp = reinterpret_cast<const uint4*>(g_Vh);
    uint4 kr = __ldg(&Kp[dv * 8 + c]);
    uint4 qr = __ldg(&Qp[s * 8 + c]);
    uint4 vr = __ldg(&Vp[s * 8 + c]);
    const __half2* kh = reinterpret_cast<const __half2*>(&kr);
    const __half2* qh = reinterpret_cast<const __half2*>(&qr);
    const __half2* vh = reinterpret_cast<const __half2*>(&vr);
    float msg[8];
#pragma unroll
    for (int p = 0; p < 4; p++) {
        float2 kf = __half22float2(kh[p]);
        float2 qf = __half22float2(qh[p]);
        float2 vf = __half22float2(vh[p]);
        msg[2 * p]     = __fdividef(vf.x, 1.0f + __expf(-(kf.x + qf.x)));
        msg[2 * p + 1] = __fdividef(vf.y, 1.0f + __expf(-(kf.y + qf.y)));
    }
    float4* hp = reinterpret_cast<float4*>(g_H + (size_t)dv * DF + c * 8);
    atomicAdd(hp,     make_float4(msg[0], msg[1], msg[2], msg[3]));
    atomicAdd(hp + 1, make_float4(msg[4], msg[5], msg[6], msg[7]));
}

// ---------------- 5: BatchNorm statistics (per-column sum / sumsq) ----------------
__global__ void __launch_bounds__(256) stats_kernel(int n) {
    __shared__ float ss[256], ss2[256];
    int t = threadIdx.x;
    int col = t & 63;
    int q = t >> 6;  // 0..3
    float s = 0.0f, s2 = 0.0f;
    for (int r = blockIdx.x * 4 + q; r < n; r += gridDim.x * 4) {
        float v = g_H[(size_t)r * DF + col];
        s += v;
        s2 += v * v;
    }
    ss[t] = s; ss2[t] = s2;
    __syncthreads();
    if (t < 64) {
        float ts = ss[t] + ss[t + 64] + ss[t + 128] + ss[t + 192];
        float ts2 = ss2[t] + ss2[t + 64] + ss2[t + 128] + ss2[t + 192];
        atomicAdd(&g_sum[t], ts);
        atomicAdd(&g_sumsq[t], ts2);
    }
}

// ---------------- 6: BN affine + ReLU + residual ----------------
__global__ void __launch_bounds__(256) out_kernel(const float* __restrict__ x,
                                                  const float* __restrict__ gamma,
                                                  const float* __restrict__ beta,
                                                  float* __restrict__ out, int n) {
    __shared__ float sc[64], sh[64];
    int t = threadIdx.x;
    if (t < 64) {
        float invn = 1.0f / (float)n;
        float mean = g_sum[t] * invn;
        float var = g_sumsq[t] * invn - mean * mean;
        float s = gamma[t] * rsqrtf(var + 1e-5f);
        sc[t] = s;
        sh[t] = beta[t] - mean * s;
    }
    __syncthreads();
    const float4* H4 = reinterpret_cast<const float4*>(g_H);
    const float4* X4 = reinterpret_cast<const float4*>(x);
    float4* O4 = reinterpret_cast<float4*>(out);
    int total = n * 16;
    for (int i = blockIdx.x * blockDim.x + t; i < total; i += gridDim.x * blockDim.x) {
        int col = (i & 15) * 4;
        float4 h = H4[i];
        float4 xv = X4[i];
        float4 o;
        o.x = fmaxf(h.x * sc[col + 0] + sh[col + 0], 0.0f) + xv.x;
        o.y = fmaxf(h.y * sc[col + 1] + sh[col + 1], 0.0f) + xv.y;
        o.z = fmaxf(h.z * sc[col + 2] + sh[col + 2], 0.0f) + xv.z;
        o.w = fmaxf(h.w * sc[col + 3] + sh[col + 3], 0.0f) + xv.w;
        O4[i] = o;
    }
}

// ---------------- launch ----------------
extern "C" void kernel_launch(void* const* d_in, const int* in_sizes, int n_in,
                              void* d_out, int out_size) {
    const float* x     = (const float*)d_in[0];
    const void*  ei    = d_in[1];
    const float* Wk    = (const float*)d_in[2];
    const float* bk    = (const float*)d_in[3];
    const float* Wq    = (const float*)d_in[4];
    const float* bq    = (const float*)d_in[5];
    const float* Wv    = (const float*)d_in[6];
    const float* bv    = (const float*)d_in[7];
    const float* Ws    = (const float*)d_in[8];
    const float* bs    = (const float*)d_in[9];
    const float* gamma = (const float*)d_in[10];
    const float* beta  = (const float*)d_in[11];

    int n = in_sizes[0] / DF;
    int e = in_sizes[1] / 2;

    static bool attr_done = false;
    if (!attr_done) {
        cudaFuncSetAttribute(gemm_kernel, cudaFuncAttributeMaxDynamicSharedMemorySize,
                             GEMM_SMEM);
        attr_done = true;
    }

    init_kernel<<<1, 256>>>((const int*)ei, e);
    convert_kernel<<<(e + 255) / 256, 256>>>(ei, e);
    transw_kernel<<<(4 * DF * DF + 255) / 256, 256>>>(Wk, Wq, Wv, Ws);

    dim3 ggrid((n + RPB - 1) / RPB, 2);
    gemm_kernel<<<ggrid, 256, GEMM_SMEM>>>(x, bk, bq, 0, n);  // -> g_Kh, g_Qh
    gemm_kernel<<<ggrid, 256, GEMM_SMEM>>>(x, bv, bs, 2, n);  // -> g_Vh, g_H

    edge_kernel<<<(e * 8 + 255) / 256, 256>>>(e);
    stats_kernel<<<1024, 256>>>(n);
    out_kernel<<<2048, 256>>>(x, gamma, beta, (float*)d_out, n);
}

// round 6
// speedup vs baseline: 2.0345x; 1.1436x over previous
#include <cuda_runtime.h>
#include <cuda_fp16.h>
#include <cstdint>

#define NMAX 100000
#define EMAX 1600000
#define DF 64

// ---------------- device scratch (no allocations allowed) ----------------
__device__ __half g_Kh[NMAX * DF];
__device__ __half g_Qh[NMAX * DF];
__device__ __half g_Vh[NMAX * DF];
__device__ float  g_H[NMAX * DF];   // fp32: skip-connection, then += messages
__device__ int    g_src[EMAX];
__device__ int    g_dst[EMAX];
__device__ __half g_Wh[4 * DF * DF];  // fp16 weights, [m][c][k] row-major (k contiguous)
__device__ float  g_sum[DF];
__device__ float  g_sumsq[DF];
__device__ int    g_is64;

// ---------------- mma helpers ----------------
__device__ __forceinline__ void ldsm_x4(unsigned* r, uint32_t addr) {
    asm volatile("ldmatrix.sync.aligned.m8n8.x4.shared.b16 {%0,%1,%2,%3}, [%4];\n"
                 : "=r"(r[0]), "=r"(r[1]), "=r"(r[2]), "=r"(r[3]) : "r"(addr));
}
__device__ __forceinline__ void mma16816(float* d, const unsigned* a, const unsigned* b) {
    asm volatile(
        "mma.sync.aligned.m16n8k16.row.col.f32.f16.f16.f32 "
        "{%0,%1,%2,%3}, {%4,%5,%6,%7}, {%8,%9}, {%0,%1,%2,%3};\n"
        : "+f"(d[0]), "+f"(d[1]), "+f"(d[2]), "+f"(d[3])
        : "r"(a[0]), "r"(a[1]), "r"(a[2]), "r"(a[3]), "r"(b[0]), "r"(b[1]));
}

// ---------------- 0: detect int64-vs-int32 edge_index; zero BN sums ----------------
__global__ void init_kernel(const int* __restrict__ ei32, int e) {
    __shared__ int any;
    int t = threadIdx.x;
    if (t == 0) any = 0;
    if (t < DF) { g_sum[t] = 0.0f; g_sumsq[t] = 0.0f; }
    __syncthreads();
    int nz = 0;
    for (int i = t; i < 1024; i += blockDim.x) {
        if (i < e) nz |= ei32[2 * i + 1];
    }
    if (nz) atomicOr(&any, 1);
    __syncthreads();
    if (t == 0) g_is64 = any ? 0 : 1;
}

// ---------------- 1: edge index -> int32 src/dst ----------------
__global__ void convert_kernel(const void* __restrict__ ei, int e) {
    int i = blockIdx.x * blockDim.x + threadIdx.x;
    if (i >= e) return;
    if (g_is64) {
        const long long* p = (const long long*)ei;
        g_src[i] = (int)p[i];
        g_dst[i] = (int)p[e + i];
    } else {
        const int* p = (const int*)ei;
        g_src[i] = p[i];
        g_dst[i] = p[e + i];
    }
}

// ---------------- 2: weights -> fp16 (natural [c][k] layout; no transpose) ----------------
__global__ void convw_kernel(const float* __restrict__ Wk, const float* __restrict__ Wq,
                             const float* __restrict__ Wv, const float* __restrict__ Ws) {
    int idx = blockIdx.x * blockDim.x + threadIdx.x;  // 0 .. 16384
    if (idx >= 4 * DF * DF) return;
    int m = idx >> 12;
    int i = idx & 4095;
    const float* W = (m == 0) ? Wk : (m == 1) ? Wq : (m == 2) ? Wv : Ws;
    g_Wh[idx] = __float2half(W[i]);
}

// ---------------- 3: tensor-core GEMM: all 4 matrices, one launch ----------------
// Block = 128 rows. x tile loaded once to fp16 smem (stride 72 halves -> ldmatrix
// phases hit banks 4r..4r+3, conflict-free), then loop m=0..3: stage W_m (64x64
// fp16), mma.sync m16n8k16 TN. Warp w owns rows [w*32, w*32+32) = two m16 tiles,
// all 64 cols = eight n8 tiles. Accum fp32; epilogue adds bias, stores fp16
// (K/Q/V) or fp32 (H).
__global__ void __launch_bounds__(128) gemm_kernel(const float* __restrict__ x,
                                                   const float* __restrict__ bk,
                                                   const float* __restrict__ bq,
                                                   const float* __restrict__ bv,
                                                   const float* __restrict__ bs,
                                                   int n) {
    __shared__ __half xs[128 * 72];
    __shared__ __half ws[64 * 72];
    int t = threadIdx.x;
    int lane = t & 31, w = t >> 5;
    int row0 = blockIdx.x * 128;

    // Stage x -> fp16 (zero-fill out-of-range rows so ldmatrix never reads junk)
    for (int idx = t; idx < 128 * 16; idx += 128) {
        int r = idx >> 4, k4 = idx & 15;
        float4 v = make_float4(0.f, 0.f, 0.f, 0.f);
        if (row0 + r < n)
            v = reinterpret_cast<const float4*>(x + (size_t)(row0 + r) * DF)[k4];
        __half2 h0 = __floats2half2_rn(v.x, v.y);
        __half2 h1 = __floats2half2_rn(v.z, v.w);
        uint2 u;
        u.x = reinterpret_cast<unsigned&>(h0);
        u.y = reinterpret_cast<unsigned&>(h1);
        *reinterpret_cast<uint2*>(&xs[r * 72 + k4 * 4]) = u;
    }

    // Precompute ldmatrix lane addresses (offsets within tiles vary per step)
    int a_row = (lane & 15);          // A: row within 16-row tile
    int a_ch  = (lane >> 4);          // A: k-half (0/1 -> +0/+8)
    int b_row = (lane & 7);           // B: row (n) within 8-row tile
    int b_ch  = (lane >> 3) & 1;      // B: k-half
    int b_nt  = (lane >> 4);          // B: which of the 2 n-tiles in an x4 load

    for (int m = 0; m < 4; m++) {
        __syncthreads();
        for (int idx = t; idx < 64 * 8; idx += 128) {   // uint4 = 8 halves
            int r = idx >> 3, k8 = idx & 7;
            uint4 v = *reinterpret_cast<const uint4*>(&g_Wh[m * 4096 + r * DF + k8 * 8]);
            *reinterpret_cast<uint4*>(&ws[r * 72 + k8 * 8]) = v;
        }
        __syncthreads();

        float acc[2][8][4];
#pragma unroll
        for (int i = 0; i < 2; i++)
#pragma unroll
            for (int j = 0; j < 8; j++)
#pragma unroll
                for (int c = 0; c < 4; c++) acc[i][j][c] = 0.0f;

#pragma unroll
        for (int ks = 0; ks < 4; ks++) {
            int k0 = ks * 16;
            unsigned a[2][4];
#pragma unroll
            for (int i = 0; i < 2; i++) {
                uint32_t addr = (uint32_t)__cvta_generic_to_shared(
                    &xs[(w * 32 + 16 * i + a_row) * 72 + k0 + a_ch * 8]);
                ldsm_x4(a[i], addr);
            }
            unsigned b[8][2];
#pragma unroll
            for (int j2 = 0; j2 < 4; j2++) {
                uint32_t addr = (uint32_t)__cvta_generic_to_shared(
                    &ws[(16 * j2 + 8 * b_nt + b_row) * 72 + k0 + b_ch * 8]);
                unsigned r4[4];
                ldsm_x4(r4, addr);
                b[2 * j2][0] = r4[0];     b[2 * j2][1] = r4[1];
                b[2 * j2 + 1][0] = r4[2]; b[2 * j2 + 1][1] = r4[3];
            }
#pragma unroll
            for (int i = 0; i < 2; i++)
#pragma unroll
                for (int j = 0; j < 8; j++)
                    mma16816(acc[i][j], a[i], b[j]);
        }

        // Epilogue
        const float* bp = (m == 0) ? bk : (m == 1) ? bq : (m == 2) ? bv : bs;
        int ra = w * 32 + (lane >> 2);
        int coff = (lane & 3) * 2;
#pragma unroll
        for (int i = 0; i < 2; i++) {
            int r0g = row0 + ra + 16 * i;
#pragma unroll
            for (int j = 0; j < 8; j++) {
                int col = j * 8 + coff;
                float bb0 = __ldg(&bp[col]);
                float bb1 = __ldg(&bp[col + 1]);
                float v0 = acc[i][j][0] + bb0, v1 = acc[i][j][1] + bb1;
                float v2 = acc[i][j][2] + bb0, v3 = acc[i][j][3] + bb1;
                if (m < 3) {
                    __half* outh = (m == 0) ? g_Kh : (m == 1) ? g_Qh : g_Vh;
                    if (r0g < n)
                        *reinterpret_cast<__half2*>(outh + (size_t)r0g * DF + col) =
                            __floats2half2_rn(v0, v1);
                    if (r0g + 8 < n)
                        *reinterpret_cast<__half2*>(outh + (size_t)(r0g + 8) * DF + col) =
                            __floats2half2_rn(v2, v3);
                } else {
                    if (r0g < n)
                        *reinterpret_cast<float2*>(g_H + (size_t)r0g * DF + col) =
                            make_float2(v0, v1);
                    if (r0g + 8 < n)
                        *reinterpret_cast<float2*>(g_H + (size_t)(r0g + 8) * DF + col) =
                            make_float2(v2, v3);
                }
            }
        }
    }
}

// ---------------- 4: edge gather (fp16) + gate + fp32 vector-atomic scatter --------------
__global__ void __launch_bounds__(256) edge_kernel(int e) {
    int idx = blockIdx.x * blockDim.x + threadIdx.x;
    if (idx >= e * 8) return;
    int ed = idx >> 3;
    int c = idx & 7;
    int s = g_src[ed];
    int dv = g_dst[ed];
    const uint4* Kp = reinterpret_cast<const uint4*>(g_Kh);
    const uint4* Qp = reinterpret_cast<const uint4*>(g_Qh);
    const uint4* Vp = reinterpret_cast<const uint4*>(g_Vh);
    uint4 kr = __ldg(&Kp[dv * 8 + c]);
    uint4 qr = __ldg(&Qp[s * 8 + c]);
    uint4 vr = __ldg(&Vp[s * 8 + c]);
    const __half2* kh = reinterpret_cast<const __half2*>(&kr);
    const __half2* qh = reinterpret_cast<const __half2*>(&qr);
    const __half2* vh = reinterpret_cast<const __half2*>(&vr);
    float msg[8];
#pragma unroll
    for (int p = 0; p < 4; p++) {
        float2 kf = __half22float2(kh[p]);
        float2 qf = __half22float2(qh[p]);
        float2 vf = __half22float2(vh[p]);
        msg[2 * p]     = __fdividef(vf.x, 1.0f + __expf(-(kf.x + qf.x)));
        msg[2 * p + 1] = __fdividef(vf.y, 1.0f + __expf(-(kf.y + qf.y)));
    }
    float4* hp = reinterpret_cast<float4*>(g_H + (size_t)dv * DF + c * 8);
    atomicAdd(hp,     make_float4(msg[0], msg[1], msg[2], msg[3]));
    atomicAdd(hp + 1, make_float4(msg[4], msg[5], msg[6], msg[7]));
}

// ---------------- 5: BatchNorm statistics (per-column sum / sumsq) ----------------
__global__ void __launch_bounds__(256) stats_kernel(int n) {
    __shared__ float ss[256], ss2[256];
    int t = threadIdx.x;
    int col = t & 63;
    int q = t >> 6;  // 0..3
    float s = 0.0f, s2 = 0.0f;
    for (int r = blockIdx.x * 4 + q; r < n; r += gridDim.x * 4) {
        float v = g_H[(size_t)r * DF + col];
        s += v;
        s2 += v * v;
    }
    ss[t] = s; ss2[t] = s2;
    __syncthreads();
    if (t < 64) {
        float ts = ss[t] + ss[t + 64] + ss[t + 128] + ss[t + 192];
        float ts2 = ss2[t] + ss2[t + 64] + ss2[t + 128] + ss2[t + 192];
        atomicAdd(&g_sum[t], ts);
        atomicAdd(&g_sumsq[t], ts2);
    }
}

// ---------------- 6: BN affine + ReLU + residual ----------------
__global__ void __launch_bounds__(256) out_kernel(const float* __restrict__ x,
                                                  const float* __restrict__ gamma,
                                                  const float* __restrict__ beta,
                                                  float* __restrict__ out, int n) {
    __shared__ float sc[64], sh[64];
    int t = threadIdx.x;
    if (t < 64) {
        float invn = 1.0f / (float)n;
        float mean = g_sum[t] * invn;
        float var = g_sumsq[t] * invn - mean * mean;
        float s = gamma[t] * rsqrtf(var + 1e-5f);
        sc[t] = s;
        sh[t] = beta[t] - mean * s;
    }
    __syncthreads();
    const float4* H4 = reinterpret_cast<const float4*>(g_H);
    const float4* X4 = reinterpret_cast<const float4*>(x);
    float4* O4 = reinterpret_cast<float4*>(out);
    int total = n * 16;
    for (int i = blockIdx.x * blockDim.x + t; i < total; i += gridDim.x * blockDim.x) {
        int col = (i & 15) * 4;
        float4 h = H4[i];
        float4 xv = X4[i];
        float4 o;
        o.x = fmaxf(h.x * sc[col + 0] + sh[col + 0], 0.0f) + xv.x;
        o.y = fmaxf(h.y * sc[col + 1] + sh[col + 1], 0.0f) + xv.y;
        o.z = fmaxf(h.z * sc[col + 2] + sh[col + 2], 0.0f) + xv.z;
        o.w = fmaxf(h.w * sc[col + 3] + sh[col + 3], 0.0f) + xv.w;
        O4[i] = o;
    }
}

// ---------------- launch ----------------
extern "C" void kernel_launch(void* const* d_in, const int* in_sizes, int n_in,
                              void* d_out, int out_size) {
    const float* x     = (const float*)d_in[0];
    const void*  ei    = d_in[1];
    const float* Wk    = (const float*)d_in[2];
    const float* bk    = (const float*)d_in[3];
    const float* Wq    = (const float*)d_in[4];
    const float* bq    = (const float*)d_in[5];
    const float* Wv    = (const float*)d_in[6];
    const float* bv    = (const float*)d_in[7];
    const float* Ws    = (const float*)d_in[8];
    const float* bs    = (const float*)d_in[9];
    const float* gamma = (const float*)d_in[10];
    const float* beta  = (const float*)d_in[11];

    int n = in_sizes[0] / DF;
    int e = in_sizes[1] / 2;

    init_kernel<<<1, 256>>>((const int*)ei, e);
    convert_kernel<<<(e + 255) / 256, 256>>>(ei, e);
    convw_kernel<<<(4 * DF * DF + 255) / 256, 256>>>(Wk, Wq, Wv, Ws);

    gemm_kernel<<<(n + 127) / 128, 128>>>(x, bk, bq, bv, bs, n);

    edge_kernel<<<(e * 8 + 255) / 256, 256>>>(e);
    stats_kernel<<<1024, 256>>>(n);
    out_kernel<<<2048, 256>>>(x, gamma, beta, (float*)d_out, n);
}

// round 8
// speedup vs baseline: 2.1958x; 1.0793x over previous
#include <cuda_runtime.h>
#include <cuda_fp16.h>
#include <cstdint>

#define NMAX 100000
#define EMAX 1600000
#define DF 64

// ---------------- device scratch (no allocations allowed) ----------------
__device__ __half g_Kh[NMAX * DF];
__device__ __half g_Qh[NMAX * DF];
__device__ __half g_Vh[NMAX * DF];
__device__ float  g_H[NMAX * DF];   // fp32: skip-connection, then += messages
__device__ int    g_src[EMAX];
__device__ int    g_dst[EMAX];
__device__ __half g_Wh[4 * DF * DF];  // fp16 weights, [m][c][k] row-major (k contiguous)
__device__ float  g_sum[DF];
__device__ float  g_sumsq[DF];
__device__ int    g_is64;

// ---------------- mma helpers ----------------
__device__ __forceinline__ void ldsm_x4(unsigned* r, uint32_t addr) {
    asm volatile("ldmatrix.sync.aligned.m8n8.x4.shared.b16 {%0,%1,%2,%3}, [%4];\n"
                 : "=r"(r[0]), "=r"(r[1]), "=r"(r[2]), "=r"(r[3]) : "r"(addr));
}
__device__ __forceinline__ void mma16816(float* d, const unsigned* a, const unsigned* b) {
    asm volatile(
        "mma.sync.aligned.m16n8k16.row.col.f32.f16.f16.f32 "
        "{%0,%1,%2,%3}, {%4,%5,%6,%7}, {%8,%9}, {%0,%1,%2,%3};\n"
        : "+f"(d[0]), "+f"(d[1]), "+f"(d[2]), "+f"(d[3])
        : "r"(a[0]), "r"(a[1]), "r"(a[2]), "r"(a[3]), "r"(b[0]), "r"(b[1]));
}

// ---------------- 0: detect int64-vs-int32 edge_index; zero BN sums ----------------
__global__ void init_kernel(const int* __restrict__ ei32, int e) {
    __shared__ int any;
    int t = threadIdx.x;
    if (t == 0) any = 0;
    if (t < DF) { g_sum[t] = 0.0f; g_sumsq[t] = 0.0f; }
    __syncthreads();
    int nz = 0;
    for (int i = t; i < 1024; i += blockDim.x) {
        if (i < e) nz |= ei32[2 * i + 1];
    }
    if (nz) atomicOr(&any, 1);
    __syncthreads();
    if (t == 0) g_is64 = any ? 0 : 1;
}

// ---------------- 1: edge index -> int32 src/dst ----------------
__global__ void convert_kernel(const void* __restrict__ ei, int e) {
    int i = blockIdx.x * blockDim.x + threadIdx.x;
    if (i >= e) return;
    if (g_is64) {
        const long long* p = (const long long*)ei;
        g_src[i] = (int)p[i];
        g_dst[i] = (int)p[e + i];
    } else {
        const int* p = (const int*)ei;
        g_src[i] = p[i];
        g_dst[i] = p[e + i];
    }
}

// ---------------- 2: weights -> fp16 (natural [c][k] layout; no transpose) ----------------
__global__ void convw_kernel(const float* __restrict__ Wk, const float* __restrict__ Wq,
                             const float* __restrict__ Wv, const float* __restrict__ Ws) {
    int idx = blockIdx.x * blockDim.x + threadIdx.x;  // 0 .. 16384
    if (idx >= 4 * DF * DF) return;
    int m = idx >> 12;
    int i = idx & 4095;
    const float* W = (m == 0) ? Wk : (m == 1) ? Wq : (m == 2) ? Wv : Ws;
    g_Wh[idx] = __float2half(W[i]);
}

// ---------------- 3: tensor-core GEMM: all 4 matrices, one launch, one sync ------------
// Block: 128 rows, 256 threads (8 warps). Stage x-tile + ALL 4 weight matrices in
// smem, single __syncthreads. Warp task = 32 rows x 32 cols for all 4 matrices:
//   row-group rt = w>>1 (rows rt*32..+32), col-half ch = w&1 (cols ch*32..+32).
// A-fragments (row-only) loaded ONCE and reused across the 4 matrices; per matrix
// only B ldmatrix + 32 mma + epilogue. smem stride 72 halves -> ldmatrix phases
// hit banks 4r..4r+3, conflict-free.
#define GEMM_SMEM ((128 * 72 + 4 * 64 * 72) * 2)

__global__ void __launch_bounds__(256) gemm_kernel(const float* __restrict__ x,
                                                   const float* __restrict__ bk,
                                                   const float* __restrict__ bq,
                                                   const float* __restrict__ bv,
                                                   const float* __restrict__ bs,
                                                   int n) {
    extern __shared__ __half smh[];
    __half* xs = smh;                 // [128][72]
    __half* ws = smh + 128 * 72;      // [4][64][72]
    int t = threadIdx.x;
    int lane = t & 31, w = t >> 5;
    int row0 = blockIdx.x * 128;

    // Stage x -> fp16 (zero-fill OOB rows)
    for (int idx = t; idx < 128 * 16; idx += 256) {
        int r = idx >> 4, k4 = idx & 15;
        float4 v = make_float4(0.f, 0.f, 0.f, 0.f);
        if (row0 + r < n)
            v = reinterpret_cast<const float4*>(x + (size_t)(row0 + r) * DF)[k4];
        __half2 h0 = __floats2half2_rn(v.x, v.y);
        __half2 h1 = __floats2half2_rn(v.z, v.w);
        uint2 u;
        u.x = reinterpret_cast<unsigned&>(h0);
        u.y = reinterpret_cast<unsigned&>(h1);
        *reinterpret_cast<uint2*>(&xs[r * 72 + k4 * 4]) = u;
    }
    // Stage all 4 weight matrices
    for (int idx = t; idx < 4 * 64 * 8; idx += 256) {   // uint4 = 8 halves
        int mr = idx >> 3, k8 = idx & 7;                 // mr = m*64 + r
        uint4 v = *reinterpret_cast<const uint4*>(&g_Wh[mr * DF + k8 * 8]);
        *reinterpret_cast<uint4*>(&ws[mr * 72 + k8 * 8]) = v;
    }
    __syncthreads();

    int rt = w >> 1;          // row-group 0..3 (32 rows each)
    int ch = w & 1;           // col-half 0..1 (32 cols each)
    int a_row = lane & 15;
    int a_ch  = lane >> 4;
    int b_row = lane & 7;
    int b_ch  = (lane >> 3) & 1;
    int b_nt  = lane >> 4;

    // A fragments: 2 m16 tiles x 4 ks, loaded once, reused for all 4 matrices
    unsigned a[2][4][4];
#pragma unroll
    for (int i = 0; i < 2; i++)
#pragma unroll
        for (int ks = 0; ks < 4; ks++) {
            uint32_t addr = (uint32_t)__cvta_generic_to_shared(
                &xs[(rt * 32 + 16 * i + a_row) * 72 + ks * 16 + a_ch * 8]);
            ldsm_x4(a[i][ks], addr);
        }

    int ra = (lane >> 2);
    int coff = (lane & 3) * 2;

#pragma unroll
    for (int m = 0; m < 4; m++) {
        float acc[2][4][4];
#pragma unroll
        for (int i = 0; i < 2; i++)
#pragma unroll
            for (int j = 0; j < 4; j++)
#pragma unroll
                for (int c = 0; c < 4; c++) acc[i][j][c] = 0.0f;

#pragma unroll
        for (int ks = 0; ks < 4; ks++) {
            // B: 4 n8 tiles at cols ch*32..+32 -> two x4 loads (16 n-rows each)
            unsigned b[4][2];
#pragma unroll
            for (int h = 0; h < 2; h++) {
                uint32_t addr = (uint32_t)__cvta_generic_to_shared(
                    &ws[(m * 64 + ch * 32 + h * 16 + 8 * b_nt + b_row) * 72 +
                        ks * 16 + b_ch * 8]);
                unsigned r4[4];
                ldsm_x4(r4, addr);
                b[2 * h][0] = r4[0];     b[2 * h][1] = r4[1];
                b[2 * h + 1][0] = r4[2]; b[2 * h + 1][1] = r4[3];
            }
#pragma unroll
            for (int i = 0; i < 2; i++)
#pragma unroll
                for (int j = 0; j < 4; j++)
                    mma16816(acc[i][j], a[i][ks], b[j]);
        }

        // Epilogue
        const float* bp = (m == 0) ? bk : (m == 1) ? bq : (m == 2) ? bv : bs;
        float bb[4][2];
#pragma unroll
        for (int j = 0; j < 4; j++) {
            int col = ch * 32 + j * 8 + coff;
            bb[j][0] = __ldg(&bp[col]);
            bb[j][1] = __ldg(&bp[col + 1]);
        }
#pragma unroll
        for (int i = 0; i < 2; i++) {
            int r0g = row0 + rt * 32 + 16 * i + ra;
#pragma unroll
            for (int j = 0; j < 4; j++) {
                int col = ch * 32 + j * 8 + coff;
                float v0 = acc[i][j][0] + bb[j][0], v1 = acc[i][j][1] + bb[j][1];
                float v2 = acc[i][j][2] + bb[j][0], v3 = acc[i][j][3] + bb[j][1];
                if (m < 3) {
                    __half* outh = (m == 0) ? g_Kh : (m == 1) ? g_Qh : g_Vh;
                    if (r0g < n)
                        *reinterpret_cast<__half2*>(outh + (size_t)r0g * DF + col) =
                            __floats2half2_rn(v0, v1);
                    if (r0g + 8 < n)
                        *reinterpret_cast<__half2*>(outh + (size_t)(r0g + 8) * DF + col) =
                            __floats2half2_rn(v2, v3);
                } else {
                    if (r0g < n)
                        *reinterpret_cast<float2*>(g_H + (size_t)r0g * DF + col) =
                            make_float2(v0, v1);
                    if (r0g + 8 < n)
                        *reinterpret_cast<float2*>(g_H + (size_t)(r0g + 8) * DF + col) =
                            make_float2(v2, v3);
                }
            }
        }
    }
}

// ---------------- 4: edge gather (fp16) + gate + fp32 vector-atomic scatter --------------
__global__ void __launch_bounds__(256) edge_kernel(int e) {
    int idx = blockIdx.x * blockDim.x + threadIdx.x;
    if (idx >= e * 8) return;
    int ed = idx >> 3;
    int c = idx & 7;
    int s = g_src[ed];
    int dv = g_dst[ed];
    const uint4* Kp = reinterpret_cast<const uint4*>(g_Kh);
    const uint4* Qp = reinterpret_cast<const uint4*>(g_Qh);
    const uint4* Vp = reinterpret_cast<const uint4*>(g_Vh);
    uint4 kr = __ldg(&Kp[dv * 8 + c]);
    uint4 qr = __ldg(&Qp[s * 8 + c]);
    uint4 vr = __ldg(&Vp[s * 8 + c]);
    const __half2* kh = reinterpret_cast<const __half2*>(&kr);
    const __half2* qh = reinterpret_cast<const __half2*>(&qr);
    const __half2* vh = reinterpret_cast<const __half2*>(&vr);
    float msg[8];
#pragma unroll
    for (int p = 0; p < 4; p++) {
        float2 kf = __half22float2(kh[p]);
        float2 qf = __half22float2(qh[p]);
        float2 vf = __half22float2(vh[p]);
        msg[2 * p]     = __fdividef(vf.x, 1.0f + __expf(-(kf.x + qf.x)));
        msg[2 * p + 1] = __fdividef(vf.y, 1.0f + __expf(-(kf.y + qf.y)));
    }
    float4* hp = reinterpret_cast<float4*>(g_H + (size_t)dv * DF + c * 8);
    atomicAdd(hp,     make_float4(msg[0], msg[1], msg[2], msg[3]));
    atomicAdd(hp + 1, make_float4(msg[4], msg[5], msg[6], msg[7]));
}

// ---------------- 5: BatchNorm statistics (per-column sum / sumsq) ----------------
__global__ void __launch_bounds__(256) stats_kernel(int n) {
    __shared__ float ss[256], ss2[256];
    int t = threadIdx.x;
    int col = t & 63;
    int q = t >> 6;  // 0..3
    float s = 0.0f, s2 = 0.0f;
    for (int r = blockIdx.x * 4 + q; r < n; r += gridDim.x * 4) {
        float v = g_H[(size_t)r * DF + col];
        s += v;
        s2 += v * v;
    }
    ss[t] = s; ss2[t] = s2;
    __syncthreads();
    if (t < 64) {
        float ts = ss[t] + ss[t + 64] + ss[t + 128] + ss[t + 192];
        float ts2 = ss2[t] + ss2[t + 64] + ss2[t + 128] + ss2[t + 192];
        atomicAdd(&g_sum[t], ts);
        atomicAdd(&g_sumsq[t], ts2);
    }
}

// ---------------- 6: BN affine + ReLU + residual ----------------
__global__ void __launch_bounds__(256) out_kernel(const float* __restrict__ x,
                                                  const float* __restrict__ gamma,
                                                  const float* __restrict__ beta,
                                                  float* __restrict__ out, int n) {
    __shared__ float sc[64], sh[64];
    int t = threadIdx.x;
    if (t < 64) {
        float invn = 1.0f / (float)n;
        float mean = g_sum[t] * invn;
        float var = g_sumsq[t] * invn - mean * mean;
        float s = gamma[t] * rsqrtf(var + 1e-5f);
        sc[t] = s;
        sh[t] = beta[t] - mean * s;
    }
    __syncthreads();
    const float4* H4 = reinterpret_cast<const float4*>(g_H);
    const float4* X4 = reinterpret_cast<const float4*>(x);
    float4* O4 = reinterpret_cast<float4*>(out);
    int total = n * 16;
    for (int i = blockIdx.x * blockDim.x + t; i < total; i += gridDim.x * blockDim.x) {
        int col = (i & 15) * 4;
        float4 h = H4[i];
        float4 xv = X4[i];
        float4 o;
        o.x = fmaxf(h.x * sc[col + 0] + sh[col + 0], 0.0f) + xv.x;
        o.y = fmaxf(h.y * sc[col + 1] + sh[col + 1], 0.0f) + xv.y;
        o.z = fmaxf(h.z * sc[col + 2] + sh[col + 2], 0.0f) + xv.z;
        o.w = fmaxf(h.w * sc[col + 3] + sh[col + 3], 0.0f) + xv.w;
        O4[i] = o;
    }
}

// ---------------- launch ----------------
extern "C" void kernel_launch(void* const* d_in, const int* in_sizes, int n_in,
                              void* d_out, int out_size) {
    const float* x     = (const float*)d_in[0];
    const void*  ei    = d_in[1];
    const float* Wk    = (const float*)d_in[2];
    const float* bk    = (const float*)d_in[3];
    const float* Wq    = (const float*)d_in[4];
    const float* bq    = (const float*)d_in[5];
    const float* Wv    = (const float*)d_in[6];
    const float* bv    = (const float*)d_in[7];
    const float* Ws    = (const float*)d_in[8];
    const float* bs    = (const float*)d_in[9];
    const float* gamma = (const float*)d_in[10];
    const float* beta  = (const float*)d_in[11];

    int n = in_sizes[0] / DF;
    int e = in_sizes[1] / 2;

    static bool attr_done = false;
    if (!attr_done) {
        cudaFuncSetAttribute(gemm_kernel, cudaFuncAttributeMaxDynamicSharedMemorySize,
                             GEMM_SMEM);
        attr_done = true;
    }

    init_kernel<<<1, 256>>>((const int*)ei, e);
    convert_kernel<<<(e + 255) / 256, 256>>>(ei, e);
    convw_kernel<<<(4 * DF * DF + 255) / 256, 256>>>(Wk, Wq, Wv, Ws);

    gemm_kernel<<<(n + 127) / 128, 256, GEMM_SMEM>>>(x, bk, bq, bv, bs, n);

    edge_kernel<<<(e * 8 + 255) / 256, 256>>>(e);
    stats_kernel<<<1024, 256>>>(n);
    out_kernel<<<2048, 256>>>(x, gamma, beta, (float*)d_out, n);
}